// round 7
// baseline (speedup 1.0000x reference)
#include <cuda_runtime.h>

#define NTOK 32768
#define NH 32
#define NCH 9                 // float4 feature chunks per token (36 floats)
#define SLICE (NCH * NTOK)

// Feature slices: 0..9 obs inputs, 10..19 obs outputs, 20..21 pred ping-pong.
__device__ float4 g_ftr[22 * SLICE];

// Precomputed folded weights
__device__ float g_M[36 * 36];     // (Wq^T Wk)/sqrt(34), [i][j], zero-padded
__device__ float g_kb[36];         // (Wk^T bq)/sqrt(34)
__device__ float g_qb[36];         // (Wq^T bk)/sqrt(34)
__device__ float g_cc[1];          // (bq.bk)/sqrt(34)
__device__ float g_cv[36][32];     // CV[j][k]
__device__ float g_cb2[32];
__device__ float g_f2h[32][32];    // [i][k] = f2w[k][i] - colmean
__device__ float g_bh[32];

typedef unsigned long long u64;

__device__ __forceinline__ u64 pack2(float lo, float hi) {
    u64 r; asm("mov.b64 %0, {%1, %2};" : "=l"(r) : "f"(lo), "f"(hi)); return r;
}
__device__ __forceinline__ void unpack2(u64 v, float& lo, float& hi) {
    asm("mov.b64 {%0, %1}, %2;" : "=f"(lo), "=f"(hi) : "l"(v));
}
__device__ __forceinline__ u64 ffma2(u64 a, u64 b, u64 c) {
    u64 d; asm("fma.rn.f32x2 %0, %1, %2, %3;" : "=l"(d) : "l"(a), "l"(b), "l"(c)); return d;
}
__device__ __forceinline__ u64 fadd2(u64 a, u64 b) {
    u64 d; asm("add.rn.f32x2 %0, %1, %2;" : "=l"(d) : "l"(a), "l"(b)); return d;
}

// ---------------------------------------------------------------------------
__global__ void __launch_bounds__(256) precomp_kernel(
    const float* __restrict__ ipw, const float* __restrict__ ipb,
    const float* __restrict__ opw, const float* __restrict__ opb,
    const float* __restrict__ saw, const float* __restrict__ sab,
    const float* __restrict__ f2w, const float* __restrict__ f2b)
{
    __shared__ float sCW[32][34];
    int tid = threadIdx.x;
    const float SC = 0.17149858514250882f;

    for (int idx = tid; idx < 36 * 36; idx += 256) {
        int i = idx / 36, j = idx % 36;
        float acc = 0.f;
        if (i < 34 && j < 34)
            for (int e = 0; e < 34; e++) acc += ipw[e * 34 + i] * ipw[(34 + e) * 34 + j];
        g_M[idx] = acc * SC;
    }
    for (int j = tid; j < 36; j += 256) {
        float a = 0.f, b = 0.f;
        if (j < 34)
            for (int e = 0; e < 34; e++) {
                a += ipb[e] * ipw[(34 + e) * 34 + j];
                b += ipw[e * 34 + j] * ipb[34 + e];
            }
        g_kb[j] = a * SC;
        g_qb[j] = b * SC;
    }
    if (tid == 0) {
        float c = 0.f;
        for (int e = 0; e < 34; e++) c += ipb[e] * ipb[34 + e];
        g_cc[0] = c * SC;
    }
    for (int idx = tid; idx < 32 * 34; idx += 256) {
        int k = idx / 34, i = idx % 34;
        float acc = 0.f;
        for (int t = 0; t < 34; t++) acc += saw[k * 34 + t] * opw[t * 34 + i];
        sCW[k][i] = acc;
    }
    __syncthreads();
    for (int idx = tid; idx < 36 * 32; idx += 256) {
        int j = idx / 32, k = idx % 32;
        float acc = 0.f;
        if (j < 34)
            for (int i = 0; i < 34; i++) acc += sCW[k][i] * ipw[(68 + i) * 34 + j];
        g_cv[j][k] = acc;
    }
    for (int k = tid; k < 32; k += 256) {
        float acc = sab[k];
        for (int t = 0; t < 34; t++) acc += saw[k * 34 + t] * opb[t];
        for (int i = 0; i < 34; i++) acc += sCW[k][i] * ipb[68 + i];
        g_cb2[k] = acc;
    }
    for (int idx = tid; idx < 32 * 32; idx += 256) {
        int i = idx / 32, k = idx % 32;
        float mu = 0.f;
        for (int kk = 0; kk < 32; kk++) mu += f2w[kk * 32 + i];
        g_f2h[i][k] = f2w[k * 32 + i] - mu * (1.f / 32.f);
    }
    for (int k = tid; k < 32; k += 256) {
        float mb = 0.f;
        for (int kk = 0; kk < 32; kk++) mb += f2b[kk];
        g_bh[k] = f2b[k] - mb * (1.f / 32.f);
    }
}

// ---------------------------------------------------------------------------
__global__ void __launch_bounds__(128) prep_kernel(const float* __restrict__ x)
{
    int n = blockIdx.x * 128 + threadIdx.x;
    int z = blockIdx.z;
    const float4* h4 = reinterpret_cast<const float4*>(x + ((size_t)z * NTOK + n) * NH);
    float4* o = g_ftr + (size_t)z * SLICE + n;
#pragma unroll
    for (int c = 0; c < 8; c++) o[(size_t)c * NTOK] = h4[c];
    int p = n & 4095;
    float4 lab;
    lab.x = (float)(p >> 6) * (1.f / 64.f);
    lab.y = (float)(p & 63) * (1.f / 64.f);
    lab.z = 0.f; lab.w = 0.f;
    o[(size_t)8 * NTOK] = lab;
}

// ---------------------------------------------------------------------------
// step kernel: 2 warps per 32-token group (hf = warp parity).
//   hf=0: chunks 0..4 (a/fbar halves t=0..9, CV j=0..19, fc2 i=0..15)
//   hf=1: chunks 5..8 (t=10..17,        CV j=20..33, fc2 i=16..31)
// ---------------------------------------------------------------------------

template<int T0, int NT>
__device__ __forceinline__ void a_gemv(const float* f4f, const float (*sM)[36],
                                       const float* sKB, u64* a)
{
#pragma unroll
    for (int t = 0; t < NT; t++) a[t] = *reinterpret_cast<const u64*>(&sKB[2 * (T0 + t)]);
#pragma unroll
    for (int i = 0; i < 34; i++) {
        u64 fp = pack2(f4f[i], f4f[i]);
#pragma unroll
        for (int t = 0; t < NT; t++)
            a[t] = ffma2(fp, *reinterpret_cast<const u64*>(&sM[i][2 * (T0 + t)]), a[t]);
    }
}

template<int C0, int NCK>
__device__ __forceinline__ void score_part(const float4* __restrict__ fin, const int* jt,
                                           const u64* a, float* psc)
{
#pragma unroll
    for (int s = 0; s < 9; s++) {
        const float4* fp4 = fin + (size_t)C0 * NTOK + jt[s];
        u64 d0 = 0ull, d1 = 0ull;
#pragma unroll
        for (int c = 0; c < NCK; c++) {
            ulonglong2 v = *reinterpret_cast<const ulonglong2*>(&fp4[(size_t)c * NTOK]);
            d0 = ffma2(a[2 * c], v.x, d0);
            d1 = ffma2(a[2 * c + 1], v.y, d1);
        }
        float x0, x1, x2, x3;
        unpack2(d0, x0, x1); unpack2(d1, x2, x3);
        psc[s] = (x0 + x1) + (x2 + x3);
    }
}

template<int C0, int NCK>
__device__ __forceinline__ void fbar_acc(const float4* __restrict__ fin, const int* jt,
                                         const float* e, float* fbf)
{
    u64 fb[2 * NCK];
#pragma unroll
    for (int t = 0; t < 2 * NCK; t++) fb[t] = 0ull;
#pragma unroll
    for (int s = 0; s < 9; s++) {
        u64 ep = pack2(e[s], e[s]);
        const float4* fp4 = fin + (size_t)C0 * NTOK + jt[s];
#pragma unroll
        for (int c = 0; c < NCK; c++) {
            ulonglong2 v = *reinterpret_cast<const ulonglong2*>(&fp4[(size_t)c * NTOK]);
            fb[2 * c]     = ffma2(ep, v.x, fb[2 * c]);
            fb[2 * c + 1] = ffma2(ep, v.y, fb[2 * c + 1]);
        }
    }
#pragma unroll
    for (int t = 0; t < 2 * NCK; t++) unpack2(fb[t], fbf[2 * t], fbf[2 * t + 1]);
}

template<int J0, int NJ>
__device__ __forceinline__ void cv_gemv(const float* fbf, const float (*sCV)[32], u64* zp)
{
#pragma unroll
    for (int j = 0; j < NJ; j++) {
        u64 fp = pack2(fbf[j], fbf[j]);
#pragma unroll
        for (int t = 0; t < 16; t++)
            zp[t] = ffma2(fp, *reinterpret_cast<const u64*>(&sCV[J0 + j][2 * t]), zp[t]);
    }
}

template<int I0>
__device__ __forceinline__ void f2_gemv(const float* zf, const float (*sF2)[32], u64* vp)
{
#pragma unroll
    for (int ii = 0; ii < 16; ii++) {
        u64 fp = pack2(zf[I0 + ii], zf[I0 + ii]);
#pragma unroll
        for (int t = 0; t < 16; t++)
            vp[t] = ffma2(fp, *reinterpret_cast<const u64*>(&sF2[I0 + ii][2 * t]), vp[t]);
    }
}

__global__ void __launch_bounds__(128) step_kernel(
    int fin_slice, int fout_slice, float* __restrict__ outbase, int zmul,
    const float* __restrict__ lng, const float* __restrict__ lnb)
{
    __shared__ __align__(16) float sM[36][36];
    __shared__ __align__(16) float sCV[36][32];
    __shared__ __align__(16) float sF2[32][32];
    __shared__ __align__(16) float sKB[36];
    __shared__ float sQB[36], sCB2[32], sBH[32], sG[32], sBB[32];
    __shared__ float sCC;
    __shared__ float s_sc[4][9][32];              // partial scores
    __shared__ __align__(16) u64 s_x[4][16][33];  // partial z / v exchange (lane-padded)

    int tid = threadIdx.x;
    for (int idx = tid; idx < 36 * 36; idx += 128) sM[idx / 36][idx % 36] = g_M[idx];
    for (int idx = tid; idx < 36 * 32; idx += 128) sCV[idx / 32][idx % 32] = g_cv[idx / 32][idx % 32];
    for (int idx = tid; idx < 32 * 32; idx += 128) sF2[idx / 32][idx % 32] = g_f2h[idx / 32][idx % 32];
    if (tid < 36) { sKB[tid] = g_kb[tid]; sQB[tid] = g_qb[tid]; }
    if (tid < 32) {
        sCB2[tid] = g_cb2[tid]; sBH[tid] = g_bh[tid];
        sG[tid] = lng[tid];     sBB[tid] = lnb[tid];
    }
    if (tid == 0) sCC = g_cc[0];
    __syncthreads();

    int w = tid >> 5, lane = tid & 31;
    int grp = w >> 1, hf = w & 1;   // warp-uniform
    int pw = w ^ 1;                 // partner warp

    int z = blockIdx.z;
    const float4* fin = g_ftr + (size_t)(fin_slice + z * zmul) * SLICE;
    float4* fout      = g_ftr + (size_t)(fout_slice + z * zmul) * SLICE;
    float* out        = outbase + (size_t)z * zmul * NTOK * NH;

    int n = blockIdx.x * 64 + grp * 32 + lane;
    int p = n & 4095;
    int row = p >> 6, col = p & 63;
    int rs = row + (row == 0) - (row == 63);
    int cs = col + (col == 0) - (col == 63);
    int jb = (n >> 12) * 4096;

    int jt[9];
#pragma unroll
    for (int s = 0; s < 9; s++) {
        int dr = s / 3 - 1, dc = s % 3 - 1;
        jt[s] = jb + (rs + dr) * 64 + (cs + dc);
    }

    // center features (full, both warps)
    float f4f[36];
#pragma unroll
    for (int c = 0; c < 9; c++) {
        float4 v = fin[(size_t)c * NTOK + jt[4]];
        f4f[4 * c + 0] = v.x; f4f[4 * c + 1] = v.y;
        f4f[4 * c + 2] = v.z; f4f[4 * c + 3] = v.w;
    }
    float c4 = sCC;
#pragma unroll
    for (int i = 0; i < 34; i++) c4 += f4f[i] * sQB[i];

    // partial a-GEMV + partial scores
    float psc[9];
    u64 a0arr[10];
    if (hf == 0) {
        a_gemv<0, 10>(f4f, sM, sKB, a0arr);
        score_part<0, 5>(fin, jt, a0arr, psc);
    } else {
        a_gemv<10, 8>(f4f, sM, sKB, a0arr);
        score_part<5, 4>(fin, jt, a0arr, psc);
    }
#pragma unroll
    for (int s = 0; s < 9; s++) s_sc[w][s][lane] = psc[s];
    __syncthreads();

    // full scores -> normalized weights (no max subtraction; scores are O(1))
    float e[9], l = 0.f;
#pragma unroll
    for (int s = 0; s < 9; s++) {
        float sc = psc[s] + s_sc[pw][s][lane] + c4;
        e[s] = __expf(sc);
        l += e[s];
    }
    float rl = 1.f / l;
#pragma unroll
    for (int s = 0; s < 9; s++) e[s] *= rl;

    // weighted feature mean over own chunks (L1-hot reload)
    float fbf[20];
    u64 zp[16];
    if (hf == 0) {
        fbar_acc<0, 5>(fin, jt, e, fbf);
        // zp = cb2 + h
#pragma unroll
        for (int t = 0; t < 16; t++) zp[t] = *reinterpret_cast<const u64*>(&sCB2[2 * t]);
#pragma unroll
        for (int c = 0; c < 8; c++) {
            ulonglong2 hv = *reinterpret_cast<const ulonglong2*>(&fin[(size_t)c * NTOK + n]);
            zp[2 * c]     = fadd2(zp[2 * c], hv.x);
            zp[2 * c + 1] = fadd2(zp[2 * c + 1], hv.y);
        }
        cv_gemv<0, 20>(fbf, sCV, zp);
    } else {
        fbar_acc<5, 4>(fin, jt, e, fbf);
#pragma unroll
        for (int t = 0; t < 16; t++) zp[t] = 0ull;
        cv_gemv<20, 14>(fbf, sCV, zp);   // j=34,35 are zero rows
    }
#pragma unroll
    for (int t = 0; t < 16; t++) s_x[w][t][lane] = zp[t];
    __syncthreads();

    float zf[32];
#pragma unroll
    for (int t = 0; t < 16; t++) {
        u64 zc = fadd2(zp[t], s_x[pw][t][lane]);
        unpack2(zc, zf[2 * t], zf[2 * t + 1]);
    }
    __syncthreads();   // all reads done before buffer reuse

    // fc2 partial (input-split)
    u64 vp[16];
    if (hf == 0) {
#pragma unroll
        for (int t = 0; t < 16; t++) vp[t] = *reinterpret_cast<const u64*>(&sBH[2 * t]);
        f2_gemv<0>(zf, sF2, vp);
    } else {
#pragma unroll
        for (int t = 0; t < 16; t++) vp[t] = 0ull;
        f2_gemv<16>(zf, sF2, vp);
    }
#pragma unroll
    for (int t = 0; t < 16; t++) s_x[w][t][lane] = vp[t];
    __syncthreads();

    float vf[32];
#pragma unroll
    for (int t = 0; t < 16; t++) {
        u64 vc = fadd2(vp[t], s_x[pw][t][lane]);
        unpack2(vc, vf[2 * t], vf[2 * t + 1]);
    }

    float var = 0.f;
#pragma unroll
    for (int k = 0; k < 32; k++) var += vf[k] * vf[k];
    float r = rsqrtf(var * (1.f / 32.f) + 1e-5f);

    // store own half of outputs
    float4* orow = reinterpret_cast<float4*>(out + (size_t)n * NH);
#pragma unroll
    for (int c4i = 0; c4i < 4; c4i++) {
        int c = 4 * hf + c4i;
        float4 y;
        y.x = vf[4 * c + 0] * r * sG[4 * c + 0] + sBB[4 * c + 0];
        y.y = vf[4 * c + 1] * r * sG[4 * c + 1] + sBB[4 * c + 1];
        y.z = vf[4 * c + 2] * r * sG[4 * c + 2] + sBB[4 * c + 2];
        y.w = vf[4 * c + 3] * r * sG[4 * c + 3] + sBB[4 * c + 3];
        orow[c] = y;
        fout[(size_t)c * NTOK + n] = y;
    }
    if (hf == 1) {
        float4 lab;
        lab.x = (float)row * (1.f / 64.f);
        lab.y = (float)col * (1.f / 64.f);
        lab.z = 0.f; lab.w = 0.f;
        fout[(size_t)8 * NTOK + n] = lab;
    }
}

// ---------------------------------------------------------------------------
extern "C" void kernel_launch(void* const* d_in, const int* in_sizes, int n_in,
                              void* d_out, int out_size)
{
    const float* x   = (const float*)d_in[0];
    const float* ipw = (const float*)d_in[1];
    const float* ipb = (const float*)d_in[2];
    const float* opw = (const float*)d_in[3];
    const float* opb = (const float*)d_in[4];
    const float* saw = (const float*)d_in[5];
    const float* sab = (const float*)d_in[6];
    const float* f2w = (const float*)d_in[7];
    const float* f2b = (const float*)d_in[8];
    const float* lng = (const float*)d_in[9];
    const float* lnb = (const float*)d_in[10];
    float* out = (float*)d_out;

    precomp_kernel<<<1, 256>>>(ipw, ipb, opw, opb, saw, sab, f2w, f2b);

    prep_kernel<<<dim3(NTOK / 128, 1, 10), 128>>>(x);

    const int NB = NTOK / 64;   // 512 blocks (2 warps/token-group, 64 tokens/block)

    // Observation: slices 0..9 -> 10..19, output rows 0..9
    step_kernel<<<dim3(NB, 1, 10), 128>>>(0, 10, out, 1, lng, lnb);

    // Prediction: 50 sequential steps; slice 19 seeds ping-pong 20/21
    for (int i = 0; i < 50; i++) {
        int fin = (i == 0) ? 19 : 20 + ((i - 1) & 1);
        int fot = 20 + (i & 1);
        float* o = out + (size_t)(10 + i) * NTOK * NH;
        step_kernel<<<dim3(NB, 1, 1), 128>>>(fin, fot, o, 0, lng, lnb);
    }
}